// round 1
// baseline (speedup 1.0000x reference)
#include <cuda_runtime.h>
#include <cuda_bf16.h>
#include <math.h>

// ---------------- Problem constants ----------------
#define BB   2
#define TT   1024
#define CC   768
#define HH   12
#define HD   64
#define LL   12
#define VV   50257
#define MM   (BB * TT)        // 2048 rows in the token dimension

// ---------------- Scratch (static device globals; no allocation) ----------
__device__ float g_x  [MM * CC];        // residual stream
__device__ float g_h  [MM * CC];        // layernorm output / GEMM input
__device__ float g_qkv[MM * 3 * CC];    // fused QKV
__device__ float g_y  [MM * CC];        // attention output
__device__ float g_fc [MM * 4 * CC];    // MLP hidden

// ---------------- Embedding ----------------
__global__ void embed_kernel(const int* __restrict__ idx,
                             const float* __restrict__ tok,
                             const float* __restrict__ pos,
                             float* __restrict__ x) {
    int i = blockIdx.x * blockDim.x + threadIdx.x;
    if (i >= MM * CC) return;
    int c  = i % CC;
    int mt = i / CC;          // b*T + t
    int t  = mt % TT;
    x[i] = tok[(long)idx[mt] * CC + c] + pos[t * CC + c];
}

// ---------------- LayerNorm (one block per row) ----------------
__global__ __launch_bounds__(256)
void ln_kernel(const float* __restrict__ in, float* __restrict__ out,
               const float* __restrict__ w, const float* __restrict__ b) {
    int row = blockIdx.x;
    const float* p = in + (long)row * CC;
    float s = 0.f, s2 = 0.f;
    for (int c = threadIdx.x; c < CC; c += 256) {
        float v = p[c];
        s += v; s2 += v * v;
    }
    __shared__ float rs[256], rs2[256];
    rs[threadIdx.x] = s; rs2[threadIdx.x] = s2;
    __syncthreads();
    for (int o = 128; o > 0; o >>= 1) {
        if (threadIdx.x < o) {
            rs [threadIdx.x] += rs [threadIdx.x + o];
            rs2[threadIdx.x] += rs2[threadIdx.x + o];
        }
        __syncthreads();
    }
    float mean = rs[0] * (1.0f / CC);
    float var  = rs2[0] * (1.0f / CC) - mean * mean;
    float inv  = rsqrtf(var + 1e-5f);
    for (int c = threadIdx.x; c < CC; c += 256) {
        float v = p[c];
        out[(long)row * CC + c] = (v - mean) * inv * w[c] + b[c];
    }
}

// ---------------- Fused causal attention: scores + softmax + AV ----------
// One block per (q, h, b). qkv layout: [B, T, 3C]; q at +0, k at +C, v at +2C.
__global__ __launch_bounds__(128)
void attn_kernel(const float* __restrict__ qkv, float* __restrict__ y) {
    int q = blockIdx.x, h = blockIdx.y, b = blockIdx.z;
    int tid = threadIdx.x;
    __shared__ float sq[HD];
    __shared__ float sc[TT];
    __shared__ float red[128];
    const float* base = qkv + (long)b * TT * 3 * CC;

    if (tid < HD) sq[tid] = base[(long)q * 3 * CC + h * HD + tid];
    __syncthreads();

    const float scale = 0.125f;   // 1/sqrt(64)
    float lmax = -1e30f;
    for (int k = tid; k <= q; k += 128) {
        const float* kp = base + (long)k * 3 * CC + CC + h * HD;
        float d = 0.f;
        #pragma unroll
        for (int e = 0; e < HD; e++) d += sq[e] * kp[e];
        d *= scale;
        sc[k] = d;
        lmax = fmaxf(lmax, d);
    }
    red[tid] = lmax; __syncthreads();
    for (int o = 64; o > 0; o >>= 1) {
        if (tid < o) red[tid] = fmaxf(red[tid], red[tid + o]);
        __syncthreads();
    }
    float mx = red[0];
    __syncthreads();

    float ls = 0.f;
    for (int k = tid; k <= q; k += 128) {
        float e = __expf(sc[k] - mx);
        sc[k] = e;
        ls += e;
    }
    red[tid] = ls; __syncthreads();
    for (int o = 64; o > 0; o >>= 1) {
        if (tid < o) red[tid] += red[tid + o];
        __syncthreads();
    }
    float inv = 1.0f / red[0];
    __syncthreads();   // before reusing red[]

    int part = tid >> 6;       // 0/1
    int d    = tid & 63;
    float acc = 0.f;
    for (int k = part; k <= q; k += 2)
        acc += sc[k] * base[(long)k * 3 * CC + 2 * CC + h * HD + d];
    red[tid] = acc; __syncthreads();
    if (tid < 64)
        y[((long)b * TT + q) * CC + h * HD + d] = (red[d] + red[d + 64]) * inv;
}

// ---------------- Tiled fp32 GEMM, 128x128x16, 8x8 microtiles ------------
// EPI: 0 = (+bias), 1 = (+bias, +residual), 2 = (+bias, exact GELU)
// TB : false -> B is [K,N] row-major ; true -> B is [N,K] row-major (B^T GEMM)
#define BM 128
#define BN 128
#define BK 16

template<bool TB, int EPI>
__global__ __launch_bounds__(256)
void gemm_kernel(const float* __restrict__ A, const float* __restrict__ B,
                 const float* __restrict__ bias, const float* __restrict__ res,
                 float* __restrict__ C_, int Ndim, int Kdim) {
    __shared__ float As[BK][BM];
    __shared__ float Bs[BK][BN];

    int t  = threadIdx.x;
    int m0 = blockIdx.y * BM;
    int n0 = blockIdx.x * BN;
    int tx = t & 15, ty = t >> 4;

    // A tile loader: 128 rows x 16 k; each thread loads 8 contiguous k's
    int aRow = t >> 1;
    int aCol = (t & 1) * 8;
    // B tile loader
    int bRow, bCol;
    if (TB) { bRow = t >> 1; bCol = (t & 1) * 8;  }  // bRow = n-in-tile, bCol = k base
    else    { bRow = t >> 4; bCol = (t & 15) * 8; }  // bRow = k,        bCol = n base

    float acc[8][8];
    #pragma unroll
    for (int i = 0; i < 8; i++)
        #pragma unroll
        for (int j = 0; j < 8; j++) acc[i][j] = 0.f;

    for (int k0 = 0; k0 < Kdim; k0 += BK) {
        // --- load A (M rows always in-bounds: M = 2048 is a multiple of 128)
        {
            const float* ap = A + (long)(m0 + aRow) * Kdim + k0 + aCol;
            float4 a0 = *(const float4*)ap;
            float4 a1 = *(const float4*)(ap + 4);
            As[aCol + 0][aRow] = a0.x; As[aCol + 1][aRow] = a0.y;
            As[aCol + 2][aRow] = a0.z; As[aCol + 3][aRow] = a0.w;
            As[aCol + 4][aRow] = a1.x; As[aCol + 5][aRow] = a1.y;
            As[aCol + 6][aRow] = a1.z; As[aCol + 7][aRow] = a1.w;
        }
        // --- load B
        if (TB) {
            int n = n0 + bRow;
            float4 b0, b1;
            if (n < Ndim) {
                const float* bp = B + (long)n * Kdim + k0 + bCol;
                b0 = *(const float4*)bp;
                b1 = *(const float4*)(bp + 4);
            } else {
                b0 = make_float4(0, 0, 0, 0);
                b1 = make_float4(0, 0, 0, 0);
            }
            Bs[bCol + 0][bRow] = b0.x; Bs[bCol + 1][bRow] = b0.y;
            Bs[bCol + 2][bRow] = b0.z; Bs[bCol + 3][bRow] = b0.w;
            Bs[bCol + 4][bRow] = b1.x; Bs[bCol + 5][bRow] = b1.y;
            Bs[bCol + 6][bRow] = b1.z; Bs[bCol + 7][bRow] = b1.w;
        } else {
            // all nn GEMMs here have N a multiple of 128 — no guard needed
            const float* bp = B + (long)(k0 + bRow) * Ndim + n0 + bCol;
            *(float4*)&Bs[bRow][bCol]     = *(const float4*)bp;
            *(float4*)&Bs[bRow][bCol + 4] = *(const float4*)(bp + 4);
        }
        __syncthreads();

        #pragma unroll
        for (int kk = 0; kk < BK; kk++) {
            float a[8], b[8];
            #pragma unroll
            for (int i = 0; i < 8; i++) a[i] = As[kk][ty * 8 + i];
            #pragma unroll
            for (int j = 0; j < 8; j++) b[j] = Bs[kk][tx * 8 + j];
            #pragma unroll
            for (int i = 0; i < 8; i++)
                #pragma unroll
                for (int j = 0; j < 8; j++)
                    acc[i][j] += a[i] * b[j];
        }
        __syncthreads();
    }

    // --- epilogue
    #pragma unroll
    for (int i = 0; i < 8; i++) {
        int m = m0 + ty * 8 + i;
        long rowOff = (long)m * Ndim;
        #pragma unroll
        for (int j = 0; j < 8; j++) {
            int n = n0 + tx * 8 + j;
            if (n < Ndim) {
                float v = acc[i][j];
                if (bias) v += bias[n];
                if (EPI == 1) v += res[rowOff + n];
                else if (EPI == 2) v = 0.5f * v * (1.0f + erff(v * 0.70710678118654752f));
                C_[rowOff + n] = v;
            }
        }
    }
}

// ---------------- Host orchestration ----------------
extern "C" void kernel_launch(void* const* d_in, const int* in_sizes, int n_in,
                              void* d_out, int out_size) {
    const int*   idx     = (const int*)  d_in[0];
    const float* tok_emb = (const float*)d_in[1];
    const float* pos_emb = (const float*)d_in[2];
    const float* ln1_w   = (const float*)d_in[3];
    const float* ln1_b   = (const float*)d_in[4];
    const float* w_qkv   = (const float*)d_in[5];
    const float* b_qkv   = (const float*)d_in[6];
    const float* w_proj  = (const float*)d_in[7];
    const float* b_proj  = (const float*)d_in[8];
    const float* ln2_w   = (const float*)d_in[9];
    const float* ln2_b   = (const float*)d_in[10];
    const float* w_fc    = (const float*)d_in[11];
    const float* b_fc    = (const float*)d_in[12];
    const float* w_fc2   = (const float*)d_in[13];
    const float* b_fc2   = (const float*)d_in[14];
    const float* lnf_w   = (const float*)d_in[15];
    const float* lnf_b   = (const float*)d_in[16];
    float* out = (float*)d_out;

    float *x, *h, *qkv, *y, *fc;
    cudaGetSymbolAddress((void**)&x,   g_x);
    cudaGetSymbolAddress((void**)&h,   g_h);
    cudaGetSymbolAddress((void**)&qkv, g_qkv);
    cudaGetSymbolAddress((void**)&y,   g_y);
    cudaGetSymbolAddress((void**)&fc,  g_fc);

    // 1. token + position embedding
    {
        int n = MM * CC;
        embed_kernel<<<(n + 255) / 256, 256>>>(idx, tok_emb, pos_emb, x);
    }

    dim3 blk(256);
    auto gemm_grid = [](int N) { return dim3((N + BN - 1) / BN, MM / BM); };

    for (int l = 0; l < LL; l++) {
        // LN1
        ln_kernel<<<MM, 256>>>(x, h, ln1_w + (long)l * CC, ln1_b + (long)l * CC);
        // QKV GEMM: [2048,768] x [768,2304]
        gemm_kernel<false, 0><<<gemm_grid(3 * CC), blk>>>(
            h, w_qkv + (long)l * CC * 3 * CC, b_qkv + (long)l * 3 * CC,
            nullptr, qkv, 3 * CC, CC);
        // fused attention
        attn_kernel<<<dim3(TT, HH, BB), 128>>>(qkv, y);
        // proj + residual: x = x + y @ w_proj + b_proj
        gemm_kernel<false, 1><<<gemm_grid(CC), blk>>>(
            y, w_proj + (long)l * CC * CC, b_proj + (long)l * CC,
            x, x, CC, CC);
        // LN2
        ln_kernel<<<MM, 256>>>(x, h, ln2_w + (long)l * CC, ln2_b + (long)l * CC);
        // FC1 + exact GELU: fc = gelu(h @ w_fc + b_fc)
        gemm_kernel<false, 2><<<gemm_grid(4 * CC), blk>>>(
            h, w_fc + (long)l * CC * 4 * CC, b_fc + (long)l * 4 * CC,
            nullptr, fc, 4 * CC, CC);
        // FC2 + residual: x = x + fc @ w_fc2 + b_fc2
        gemm_kernel<false, 1><<<gemm_grid(CC), blk>>>(
            fc, w_fc2 + (long)l * 4 * CC * CC, b_fc2 + (long)l * CC,
            x, x, CC, 4 * CC);
    }

    // final LN
    ln_kernel<<<MM, 256>>>(x, h, lnf_w, lnf_b);
    // tied head: logits = h @ tok_emb^T   (B stored [V, C] -> TB variant)
    gemm_kernel<true, 0><<<gemm_grid(VV), blk>>>(
        h, tok_emb, nullptr, nullptr, out, VV, CC);
}

// round 3
// speedup vs baseline: 4.6651x; 4.6651x over previous
#include <cuda_runtime.h>
#include <cuda_bf16.h>
#include <math.h>
#include <stdint.h>

// ---------------- Problem constants ----------------
#define BB   2
#define TT   1024
#define CC   768
#define HH   12
#define HD   64
#define LL   12
#define VV   50257
#define MM   (BB * TT)        // 2048 rows

typedef __nv_bfloat16 bf16;

// ---------------- Scratch (static device globals) ----------------
__device__ float g_x  [MM * CC];
__device__ float g_qkv[MM * 3 * CC];
__device__ __align__(16) bf16 g_ah[MM * CC];        // 768-wide activation hi
__device__ __align__(16) bf16 g_al[MM * CC];        // 768-wide activation lo
__device__ __align__(16) bf16 g_fh[MM * 4 * CC];    // 3072-wide fc hi
__device__ __align__(16) bf16 g_fl[MM * 4 * CC];    // 3072-wide fc lo
// transposed weights, [N][K] K-major per layer, hi/lo split
__device__ __align__(16) bf16 g_wqkv_h[LL * 3 * CC * CC];
__device__ __align__(16) bf16 g_wqkv_l[LL * 3 * CC * CC];
__device__ __align__(16) bf16 g_wproj_h[LL * CC * CC];
__device__ __align__(16) bf16 g_wproj_l[LL * CC * CC];
__device__ __align__(16) bf16 g_wfc_h [LL * 4 * CC * CC];
__device__ __align__(16) bf16 g_wfc_l [LL * 4 * CC * CC];
__device__ __align__(16) bf16 g_wfc2_h[LL * 4 * CC * CC];
__device__ __align__(16) bf16 g_wfc2_l[LL * 4 * CC * CC];
__device__ __align__(16) bf16 g_emb_h [VV * CC];
__device__ __align__(16) bf16 g_emb_l [VV * CC];

// ---------------- PTX helpers ----------------
__device__ __forceinline__ uint32_t smem_u32(const void* p) {
    uint32_t a;
    asm("{ .reg .u64 t; cvta.to.shared.u64 t, %1; cvt.u32.u64 %0, t; }"
        : "=r"(a) : "l"(p));
    return a;
}
__device__ __forceinline__ void cp16(uint32_t dst, const void* src, int srcsize) {
    asm volatile("cp.async.cg.shared.global [%0], [%1], 16, %2;"
                 :: "r"(dst), "l"(src), "r"(srcsize) : "memory");
}
__device__ __forceinline__ void ldm4(uint32_t r[4], uint32_t a) {
    asm volatile("ldmatrix.sync.aligned.m8n8.x4.shared.b16 {%0,%1,%2,%3}, [%4];"
                 : "=r"(r[0]), "=r"(r[1]), "=r"(r[2]), "=r"(r[3]) : "r"(a));
}
__device__ __forceinline__ void mma16816(float d[4], const uint32_t a[4],
                                         const uint32_t b[2]) {
    asm volatile(
        "mma.sync.aligned.m16n8k16.row.col.f32.bf16.bf16.f32 "
        "{%0,%1,%2,%3}, {%4,%5,%6,%7}, {%8,%9}, {%0,%1,%2,%3};"
        : "+f"(d[0]), "+f"(d[1]), "+f"(d[2]), "+f"(d[3])
        : "r"(a[0]), "r"(a[1]), "r"(a[2]), "r"(a[3]), "r"(b[0]), "r"(b[1]));
}

// ---------------- Embedding ----------------
__global__ void embed_kernel(const int* __restrict__ idx,
                             const float* __restrict__ tok,
                             const float* __restrict__ pos,
                             float* __restrict__ x) {
    int i = blockIdx.x * blockDim.x + threadIdx.x;
    if (i >= MM * CC) return;
    int c  = i % CC;
    int mt = i / CC;
    int t  = mt % TT;
    x[i] = tok[(long)idx[mt] * CC + c] + pos[t * CC + c];
}

// ---------------- LayerNorm -> bf16 hi/lo ----------------
__global__ __launch_bounds__(256)
void ln_kernel(const float* __restrict__ in,
               bf16* __restrict__ oh, bf16* __restrict__ ol,
               const float* __restrict__ w, const float* __restrict__ b) {
    int row = blockIdx.x;
    const float* p = in + (long)row * CC;
    float s = 0.f, s2 = 0.f;
    for (int c = threadIdx.x; c < CC; c += 256) {
        float v = p[c];
        s += v; s2 += v * v;
    }
    __shared__ float rs[256], rs2[256];
    rs[threadIdx.x] = s; rs2[threadIdx.x] = s2;
    __syncthreads();
    for (int o = 128; o > 0; o >>= 1) {
        if (threadIdx.x < o) {
            rs [threadIdx.x] += rs [threadIdx.x + o];
            rs2[threadIdx.x] += rs2[threadIdx.x + o];
        }
        __syncthreads();
    }
    float mean = rs[0] * (1.0f / CC);
    float var  = rs2[0] * (1.0f / CC) - mean * mean;
    float inv  = rsqrtf(var + 1e-5f);
    for (int c = threadIdx.x; c < CC; c += 256) {
        float v = (p[c] - mean) * inv * w[c] + b[c];
        bf16 h = __float2bfloat16(v);
        oh[(long)row * CC + c] = h;
        ol[(long)row * CC + c] = __float2bfloat16(v - __bfloat162float(h));
    }
}

// ---------------- fp32 -> bf16 hi/lo (embedding table) ----------------
__global__ void cvt_act(const float* __restrict__ in,
                        bf16* __restrict__ hi, bf16* __restrict__ lo, int n) {
    int i = blockIdx.x * blockDim.x + threadIdx.x;
    if (i >= n) return;
    float v = in[i];
    bf16 h = __float2bfloat16(v);
    hi[i] = h;
    lo[i] = __float2bfloat16(v - __bfloat162float(h));
}

// transpose + convert: W [K,N] row-major -> out [N,K] (layer via blockIdx.z)
__global__ __launch_bounds__(256)
void wt_cvt(const float* __restrict__ W,
            bf16* __restrict__ oh, bf16* __restrict__ ol, int K, int N) {
    __shared__ float t[32][33];
    long lofs = (long)blockIdx.z * K * N;
    int n0 = blockIdx.x * 32, k0 = blockIdx.y * 32;
    int tx = threadIdx.x & 31, ty = threadIdx.x >> 5;
    #pragma unroll
    for (int r = 0; r < 32; r += 8)
        t[ty + r][tx] = W[lofs + (long)(k0 + ty + r) * N + n0 + tx];
    __syncthreads();
    #pragma unroll
    for (int r = 0; r < 32; r += 8) {
        int n = n0 + ty + r, k = k0 + tx;
        float v = t[tx][ty + r];
        bf16 h = __float2bfloat16(v);
        long o = lofs + (long)n * K + k;
        oh[o] = h;
        ol[o] = __float2bfloat16(v - __bfloat162float(h));
    }
}

// ---------------- Flash attention (fp32 in, bf16 hi/lo out) -------------
#define AQ 64
#define AKT 64
__global__ __launch_bounds__(128)
void attn_flash(const float* __restrict__ qkv,
                bf16* __restrict__ yh, bf16* __restrict__ yl) {
    int q0 = blockIdx.x * AQ;
    int h  = blockIdx.y, b = blockIdx.z;
    int tid = threadIdx.x;
    int a = tid >> 2;              // 0..31 -> q rows 2a, 2a+1
    int dg = (tid & 3) * 16;       // dim offset
    __shared__ float sK[AKT][HD];
    __shared__ float sV[AKT][HD];
    const float* base = qkv + (long)b * TT * 3 * CC;
    const float scale = 0.125f;

    float qr[2][16], o[2][16];
    float m[2] = {-1e30f, -1e30f}, l[2] = {0.f, 0.f};
    #pragma unroll
    for (int r = 0; r < 2; r++) {
        int qg = q0 + 2 * a + r;
        #pragma unroll
        for (int i = 0; i < 16; i++) {
            qr[r][i] = base[(long)qg * 3 * CC + h * HD + dg + i] * scale;
            o[r][i] = 0.f;
        }
    }
    int nkt = q0 / AKT + 1;
    for (int kt = 0; kt < nkt; kt++) {
        int k0 = kt * AKT;
        __syncthreads();
        for (int it = tid; it < AKT * HD / 4; it += 128) {
            int row = it >> 4;
            int c4  = (it & 15) * 4;
            const float* kp = base + (long)(k0 + row) * 3 * CC + CC + h * HD + c4;
            const float* vp = base + (long)(k0 + row) * 3 * CC + 2 * CC + h * HD + c4;
            *(float4*)&sK[row][c4] = *(const float4*)kp;
            *(float4*)&sV[row][c4] = *(const float4*)vp;
        }
        __syncthreads();
        for (int jc = 0; jc < 4; jc++) {
            float s[2][16];
            #pragma unroll
            for (int j = 0; j < 16; j++) {
                int jj = jc * 16 + j;
                float p0 = 0.f, p1 = 0.f;
                #pragma unroll
                for (int i = 0; i < 16; i++) {
                    float kv = sK[jj][dg + i];
                    p0 += qr[0][i] * kv;
                    p1 += qr[1][i] * kv;
                }
                p0 += __shfl_xor_sync(0xffffffffu, p0, 1);
                p0 += __shfl_xor_sync(0xffffffffu, p0, 2);
                p1 += __shfl_xor_sync(0xffffffffu, p1, 1);
                p1 += __shfl_xor_sync(0xffffffffu, p1, 2);
                s[0][j] = p0; s[1][j] = p1;
            }
            #pragma unroll
            for (int r = 0; r < 2; r++) {
                int qg = q0 + 2 * a + r;
                float mx = m[r];
                #pragma unroll
                for (int j = 0; j < 16; j++) {
                    int kj = k0 + jc * 16 + j;
                    if (kj > qg) s[r][j] = -1e30f;
                    mx = fmaxf(mx, s[r][j]);
                }
                float corr = __expf(m[r] - mx);
                m[r] = mx;
                l[r] *= corr;
                #pragma unroll
                for (int i = 0; i < 16; i++) o[r][i] *= corr;
                #pragma unroll
                for (int j = 0; j < 16; j++) {
                    float p = __expf(s[r][j] - mx);
                    l[r] += p;
                    int jj = jc * 16 + j;
                    #pragma unroll
                    for (int i = 0; i < 16; i++)
                        o[r][i] += p * sV[jj][dg + i];
                }
            }
        }
    }
    #pragma unroll
    for (int r = 0; r < 2; r++) {
        int qg = q0 + 2 * a + r;
        float inv = 1.f / l[r];
        #pragma unroll
        for (int i = 0; i < 16; i++) {
            float v = o[r][i] * inv;
            long ofs = ((long)b * TT + qg) * CC + h * HD + dg + i;
            bf16 hh = __float2bfloat16(v);
            yh[ofs] = hh;
            yl[ofs] = __float2bfloat16(v - __bfloat162float(hh));
        }
    }
}

// ---------------- mma.sync split-bf16 GEMM ----------------
// D[M,N] = A[M,K] * B[N,K]^T fp32 via 3 bf16 MMA passes (Ah.Bh+Ah.Bl+Al.Bh)
// CTA 128x128, BK=32, 256 threads (8 warps 2x4), warp tile 64x32.
// smem per stage: 4 tiles (Ah,Al,Bh,Bl) of 128 rows x 40 bf16 (80B stride).
// EPI: 0 = +bias (fp32 out); 1 = +bias+residual (fp32 out);
//      2 = +bias, exact GELU -> bf16 hi/lo out
#define TILE_B   10240              // 128 * 80
#define STAGE_B  (4 * TILE_B)       // 40960
#define GEMM_SMEM (2 * STAGE_B)     // 81920

template<int EPI>
__global__ __launch_bounds__(256)
void mma_gemm(const bf16* __restrict__ Ah, const bf16* __restrict__ Al,
              const bf16* __restrict__ Bh, const bf16* __restrict__ Bl,
              const float* __restrict__ bias, const float* __restrict__ res,
              float* __restrict__ C, bf16* __restrict__ Ch, bf16* __restrict__ Cl,
              int Ndim, int Kdim) {
    extern __shared__ char smemraw[];
    uint32_t sb = smem_u32(smemraw);
    int tid = threadIdx.x, w = tid >> 5, lane = tid & 31;
    int m0 = blockIdx.x * 128, n0 = blockIdx.y * 128;   // m fastest -> B reuse in L2
    int wm = w >> 2, wn = w & 3;

    float acc[4][4][4];
    #pragma unroll
    for (int i = 0; i < 4; i++)
        #pragma unroll
        for (int j = 0; j < 4; j++)
            #pragma unroll
            for (int r = 0; r < 4; r++) acc[i][j][r] = 0.f;

    // per-thread load coords: row = tid/2, two 16B chunks at chunk base (tid&1)*2
    int lrow = tid >> 1;
    int lch  = (tid & 1) * 2;

    auto load_stage = [&](int s, int c) {
        int k0 = c * 32;
        uint32_t dbase = sb + s * STAGE_B + lrow * 80 + lch * 16;
        // A hi/lo
        {
            const bf16* g = Ah + (long)(m0 + lrow) * Kdim + k0 + lch * 8;
            cp16(dbase, g, 16);
            cp16(dbase + 16, g + 8, 16);
        }
        {
            const bf16* g = Al + (long)(m0 + lrow) * Kdim + k0 + lch * 8;
            cp16(dbase + TILE_B, g, 16);
            cp16(dbase + TILE_B + 16, g + 8, 16);
        }
        // B hi/lo with N-edge zfill
        int n = n0 + lrow;
        int ok = (n < Ndim);
        int nn = ok ? n : 0;
        int ssz = ok ? 16 : 0;
        {
            const bf16* g = Bh + (long)nn * Kdim + k0 + lch * 8;
            cp16(dbase + 2 * TILE_B, g, ssz);
            cp16(dbase + 2 * TILE_B + 16, g + 8, ssz);
        }
        {
            const bf16* g = Bl + (long)nn * Kdim + k0 + lch * 8;
            cp16(dbase + 3 * TILE_B, g, ssz);
            cp16(dbase + 3 * TILE_B + 16, g + 8, ssz);
        }
    };

    const int NC = Kdim >> 5;   // Kdim / 32

    load_stage(0, 0);
    asm volatile("cp.async.commit_group;" ::: "memory");

    for (int c = 0; c < NC; c++) {
        int s = c & 1;
        if (c + 1 < NC) {
            load_stage(s ^ 1, c + 1);
            asm volatile("cp.async.commit_group;" ::: "memory");
            asm volatile("cp.async.wait_group 1;" ::: "memory");
        } else {
            asm volatile("cp.async.wait_group 0;" ::: "memory");
        }
        __syncthreads();

        uint32_t base = sb + s * STAGE_B;
        #pragma unroll
        for (int kk = 0; kk < 2; kk++) {
            uint32_t ah[4][4], al[4][4], bh[4][2], bl[4][2];
            // A fragments: 4 m-tiles, ldmatrix x4
            #pragma unroll
            for (int i = 0; i < 4; i++) {
                int r  = wm * 64 + i * 16 + (lane & 15);
                int kb = kk * 16 + ((lane >> 4) << 3);
                uint32_t off = (uint32_t)(r * 80 + kb * 2);
                ldm4(ah[i], base + off);
                ldm4(al[i], base + TILE_B + off);
            }
            // B fragments: 2 x4 loads cover 4 n-tiles
            #pragma unroll
            for (int jp = 0; jp < 2; jp++) {
                int mat = lane >> 3;
                int r   = wn * 32 + jp * 16 + ((mat >> 1) << 3) + (lane & 7);
                int kb  = kk * 16 + ((mat & 1) << 3);
                uint32_t off = (uint32_t)(r * 80 + kb * 2);
                uint32_t t0[4], t1[4];
                ldm4(t0, base + 2 * TILE_B + off);
                ldm4(t1, base + 3 * TILE_B + off);
                bh[2 * jp][0] = t0[0]; bh[2 * jp][1] = t0[1];
                bh[2 * jp + 1][0] = t0[2]; bh[2 * jp + 1][1] = t0[3];
                bl[2 * jp][0] = t1[0]; bl[2 * jp][1] = t1[1];
                bl[2 * jp + 1][0] = t1[2]; bl[2 * jp + 1][1] = t1[3];
            }
            #pragma unroll
            for (int i = 0; i < 4; i++)
                #pragma unroll
                for (int j = 0; j < 4; j++) {
                    mma16816(acc[i][j], ah[i], bh[j]);
                    mma16816(acc[i][j], ah[i], bl[j]);
                    mma16816(acc[i][j], al[i], bh[j]);
                }
        }
        __syncthreads();
    }

    // ---- epilogue ----
    #pragma unroll
    for (int i = 0; i < 4; i++) {
        int row0 = m0 + wm * 64 + i * 16 + (lane >> 2);
        #pragma unroll
        for (int j = 0; j < 4; j++) {
            int col = n0 + wn * 32 + j * 8 + 2 * (lane & 3);
            #pragma unroll
            for (int r = 0; r < 4; r++) {
                int rr = row0 + (r >> 1) * 8;
                int cc = col + (r & 1);
                if (cc < Ndim) {
                    float v = acc[i][j][r];
                    if (bias) v += __ldg(bias + cc);
                    long o = (long)rr * Ndim + cc;
                    if (EPI == 1) v += res[o];
                    if (EPI == 2) {
                        v = 0.5f * v * (1.f + erff(v * 0.70710678118654752f));
                        bf16 hh = __float2bfloat16(v);
                        Ch[o] = hh;
                        Cl[o] = __float2bfloat16(v - __bfloat162float(hh));
                    } else {
                        C[o] = v;
                    }
                }
            }
        }
    }
}

// ---------------- Host orchestration ----------------
extern "C" void kernel_launch(void* const* d_in, const int* in_sizes, int n_in,
                              void* d_out, int out_size) {
    const int*   idx     = (const int*)  d_in[0];
    const float* tok_emb = (const float*)d_in[1];
    const float* pos_emb = (const float*)d_in[2];
    const float* ln1_w   = (const float*)d_in[3];
    const float* ln1_b   = (const float*)d_in[4];
    const float* w_qkv   = (const float*)d_in[5];
    const float* b_qkv   = (const float*)d_in[6];
    const float* w_proj  = (const float*)d_in[7];
    const float* b_proj  = (const float*)d_in[8];
    const float* ln2_w   = (const float*)d_in[9];
    const float* ln2_b   = (const float*)d_in[10];
    const float* w_fc    = (const float*)d_in[11];
    const float* b_fc    = (const float*)d_in[12];
    const float* w_fc2   = (const float*)d_in[13];
    const float* b_fc2   = (const float*)d_in[14];
    const float* lnf_w   = (const float*)d_in[15];
    const float* lnf_b   = (const float*)d_in[16];
    float* out = (float*)d_out;

    cudaFuncSetAttribute(mma_gemm<0>, cudaFuncAttributeMaxDynamicSharedMemorySize, GEMM_SMEM);
    cudaFuncSetAttribute(mma_gemm<1>, cudaFuncAttributeMaxDynamicSharedMemorySize, GEMM_SMEM);
    cudaFuncSetAttribute(mma_gemm<2>, cudaFuncAttributeMaxDynamicSharedMemorySize, GEMM_SMEM);

    float *x, *qkv;
    cudaGetSymbolAddress((void**)&x,   g_x);
    cudaGetSymbolAddress((void**)&qkv, g_qkv);
    bf16 *ah, *al, *fh, *fl;
    bf16 *wqh, *wql, *wph, *wpl, *wfh, *wfl, *w2h, *w2l, *eh, *el;
    cudaGetSymbolAddress((void**)&ah,  g_ah);      cudaGetSymbolAddress((void**)&al,  g_al);
    cudaGetSymbolAddress((void**)&fh,  g_fh);      cudaGetSymbolAddress((void**)&fl,  g_fl);
    cudaGetSymbolAddress((void**)&wqh, g_wqkv_h);  cudaGetSymbolAddress((void**)&wql, g_wqkv_l);
    cudaGetSymbolAddress((void**)&wph, g_wproj_h); cudaGetSymbolAddress((void**)&wpl, g_wproj_l);
    cudaGetSymbolAddress((void**)&wfh, g_wfc_h);   cudaGetSymbolAddress((void**)&wfl, g_wfc_l);
    cudaGetSymbolAddress((void**)&w2h, g_wfc2_h);  cudaGetSymbolAddress((void**)&w2l, g_wfc2_l);
    cudaGetSymbolAddress((void**)&eh,  g_emb_h);   cudaGetSymbolAddress((void**)&el,  g_emb_l);

    // ---- weight preprocessing ----
    wt_cvt<<<dim3(3 * CC / 32, CC / 32, LL), 256>>>(w_qkv,  wqh, wql, CC, 3 * CC);
    wt_cvt<<<dim3(CC / 32, CC / 32, LL), 256>>>(w_proj, wph, wpl, CC, CC);
    wt_cvt<<<dim3(4 * CC / 32, CC / 32, LL), 256>>>(w_fc,   wfh, wfl, CC, 4 * CC);
    wt_cvt<<<dim3(CC / 32, 4 * CC / 32, LL), 256>>>(w_fc2,  w2h, w2l, 4 * CC, CC);
    {
        int n = VV * CC;
        cvt_act<<<(n + 255) / 256, 256>>>(tok_emb, eh, el, n);
    }

    // ---- embedding ----
    {
        int n = MM * CC;
        embed_kernel<<<(n + 255) / 256, 256>>>(idx, tok_emb, pos_emb, x);
    }

    auto ggrid = [](int N) { return dim3(MM / 128, (N + 127) / 128); };

    for (int l = 0; l < LL; l++) {
        // LN1 -> QKV GEMM (fp32 out)
        ln_kernel<<<MM, 256>>>(x, ah, al, ln1_w + (long)l * CC, ln1_b + (long)l * CC);
        mma_gemm<0><<<ggrid(3 * CC), 256, GEMM_SMEM>>>(
            ah, al, wqh + (long)l * 3 * CC * CC, wql + (long)l * 3 * CC * CC,
            b_qkv + (long)l * 3 * CC, nullptr, qkv, nullptr, nullptr, 3 * CC, CC);
        // attention -> bf16 hi/lo (reuse ah/al)
        attn_flash<<<dim3(TT / AQ, HH, BB), 128>>>(qkv, ah, al);
        // proj + residual -> x
        mma_gemm<1><<<ggrid(CC), 256, GEMM_SMEM>>>(
            ah, al, wph + (long)l * CC * CC, wpl + (long)l * CC * CC,
            b_proj + (long)l * CC, x, x, nullptr, nullptr, CC, CC);
        // LN2 -> FC1 + GELU -> bf16 hi/lo fc
        ln_kernel<<<MM, 256>>>(x, ah, al, ln2_w + (long)l * CC, ln2_b + (long)l * CC);
        mma_gemm<2><<<ggrid(4 * CC), 256, GEMM_SMEM>>>(
            ah, al, wfh + (long)l * 4 * CC * CC, wfl + (long)l * 4 * CC * CC,
            b_fc + (long)l * 4 * CC, nullptr, nullptr, fh, fl, 4 * CC, CC);
        // FC2 + residual -> x
        mma_gemm<1><<<ggrid(CC), 256, GEMM_SMEM>>>(
            fh, fl, w2h + (long)l * 4 * CC * CC, w2l + (long)l * 4 * CC * CC,
            b_fc2 + (long)l * CC, x, x, nullptr, nullptr, CC, 4 * CC);
    }

    // final LN + tied head
    ln_kernel<<<MM, 256>>>(x, ah, al, lnf_w, lnf_b);
    mma_gemm<0><<<ggrid(VV), 256, GEMM_SMEM>>>(
        ah, al, eh, el, nullptr, nullptr, out, nullptr, nullptr, VV, CC);
}

// round 4
// speedup vs baseline: 4.9653x; 1.0643x over previous
#include <cuda_runtime.h>
#include <cuda_bf16.h>
#include <math.h>
#include <stdint.h>

// ---------------- Problem constants ----------------
#define BB   2
#define TT   1024
#define CC   768
#define HH   12
#define HD   64
#define LL   12
#define VV   50257
#define MM   (BB * TT)        // 2048 rows

typedef __nv_bfloat16 bf16;

// ---------------- Scratch (static device globals) ----------------
__device__ float g_x  [MM * CC];
__device__ float g_qkv[MM * 3 * CC];
__device__ __align__(16) bf16 g_ah[MM * CC];
__device__ __align__(16) bf16 g_al[MM * CC];
__device__ __align__(16) bf16 g_fh[MM * 4 * CC];
__device__ __align__(16) bf16 g_fl[MM * 4 * CC];
// transposed weights, [N][K] K-major per layer, hi/lo split
__device__ __align__(16) bf16 g_wqkv_h[LL * 3 * CC * CC];
__device__ __align__(16) bf16 g_wqkv_l[LL * 3 * CC * CC];
__device__ __align__(16) bf16 g_wproj_h[LL * CC * CC];
__device__ __align__(16) bf16 g_wproj_l[LL * CC * CC];
__device__ __align__(16) bf16 g_wfc_h [LL * 4 * CC * CC];
__device__ __align__(16) bf16 g_wfc_l [LL * 4 * CC * CC];
__device__ __align__(16) bf16 g_wfc2_h[LL * 4 * CC * CC];
__device__ __align__(16) bf16 g_wfc2_l[LL * 4 * CC * CC];
__device__ __align__(16) bf16 g_emb_h [VV * CC];
__device__ __align__(16) bf16 g_emb_l [VV * CC];

// ---------------- PTX helpers ----------------
__device__ __forceinline__ uint32_t smem_u32(const void* p) {
    uint32_t a;
    asm("{ .reg .u64 t; cvta.to.shared.u64 t, %1; cvt.u32.u64 %0, t; }"
        : "=r"(a) : "l"(p));
    return a;
}
__device__ __forceinline__ void cp16(uint32_t dst, const void* src, int srcsize) {
    asm volatile("cp.async.cg.shared.global [%0], [%1], 16, %2;"
                 :: "r"(dst), "l"(src), "r"(srcsize) : "memory");
}
__device__ __forceinline__ void ldm4(uint32_t r[4], uint32_t a) {
    asm volatile("ldmatrix.sync.aligned.m8n8.x4.shared.b16 {%0,%1,%2,%3}, [%4];"
                 : "=r"(r[0]), "=r"(r[1]), "=r"(r[2]), "=r"(r[3]) : "r"(a));
}
__device__ __forceinline__ void mma16816(float d[4], const uint32_t a[4],
                                         const uint32_t b[2]) {
    asm volatile(
        "mma.sync.aligned.m16n8k16.row.col.f32.bf16.bf16.f32 "
        "{%0,%1,%2,%3}, {%4,%5,%6,%7}, {%8,%9}, {%0,%1,%2,%3};"
        : "+f"(d[0]), "+f"(d[1]), "+f"(d[2]), "+f"(d[3])
        : "r"(a[0]), "r"(a[1]), "r"(a[2]), "r"(a[3]), "r"(b[0]), "r"(b[1]));
}

// ---------------- Embedding ----------------
__global__ void embed_kernel(const int* __restrict__ idx,
                             const float* __restrict__ tok,
                             const float* __restrict__ pos,
                             float* __restrict__ x) {
    int i = blockIdx.x * blockDim.x + threadIdx.x;
    if (i >= MM * CC) return;
    int c  = i % CC;
    int mt = i / CC;
    int t  = mt % TT;
    x[i] = tok[(long)idx[mt] * CC + c] + pos[t * CC + c];
}

// ---------------- LayerNorm -> bf16 hi/lo ----------------
__global__ __launch_bounds__(256)
void ln_kernel(const float* __restrict__ in,
               bf16* __restrict__ oh, bf16* __restrict__ ol,
               const float* __restrict__ w, const float* __restrict__ b) {
    int row = blockIdx.x;
    const float* p = in + (long)row * CC;
    float s = 0.f, s2 = 0.f;
    for (int c = threadIdx.x; c < CC; c += 256) {
        float v = p[c];
        s += v; s2 += v * v;
    }
    __shared__ float rs[256], rs2[256];
    rs[threadIdx.x] = s; rs2[threadIdx.x] = s2;
    __syncthreads();
    for (int o = 128; o > 0; o >>= 1) {
        if (threadIdx.x < o) {
            rs [threadIdx.x] += rs [threadIdx.x + o];
            rs2[threadIdx.x] += rs2[threadIdx.x + o];
        }
        __syncthreads();
    }
    float mean = rs[0] * (1.0f / CC);
    float var  = rs2[0] * (1.0f / CC) - mean * mean;
    float inv  = rsqrtf(var + 1e-5f);
    for (int c = threadIdx.x; c < CC; c += 256) {
        float v = (p[c] - mean) * inv * w[c] + b[c];
        bf16 h = __float2bfloat16(v);
        oh[(long)row * CC + c] = h;
        ol[(long)row * CC + c] = __float2bfloat16(v - __bfloat162float(h));
    }
}

// ---------------- fp32 -> bf16 hi/lo ----------------
__global__ void cvt_act(const float* __restrict__ in,
                        bf16* __restrict__ hi, bf16* __restrict__ lo, int n) {
    int i = blockIdx.x * blockDim.x + threadIdx.x;
    if (i >= n) return;
    float v = in[i];
    bf16 h = __float2bfloat16(v);
    hi[i] = h;
    lo[i] = __float2bfloat16(v - __bfloat162float(h));
}

// transpose + convert: W [K,N] row-major -> out [N,K] (layer via blockIdx.z)
__global__ __launch_bounds__(256)
void wt_cvt(const float* __restrict__ W,
            bf16* __restrict__ oh, bf16* __restrict__ ol, int K, int N) {
    __shared__ float t[32][33];
    long lofs = (long)blockIdx.z * K * N;
    int n0 = blockIdx.x * 32, k0 = blockIdx.y * 32;
    int tx = threadIdx.x & 31, ty = threadIdx.x >> 5;
    #pragma unroll
    for (int r = 0; r < 32; r += 8)
        t[ty + r][tx] = W[lofs + (long)(k0 + ty + r) * N + n0 + tx];
    __syncthreads();
    #pragma unroll
    for (int r = 0; r < 32; r += 8) {
        int n = n0 + ty + r, k = k0 + tx;
        float v = t[tx][ty + r];
        bf16 h = __float2bfloat16(v);
        long o = lofs + (long)n * K + k;
        oh[o] = h;
        ol[o] = __float2bfloat16(v - __bfloat162float(h));
    }
}

// ---------------- Flash attention (fp32 in, bf16 hi/lo out) -------------
#define AQ 64
#define AKT 64
__global__ __launch_bounds__(128)
void attn_flash(const float* __restrict__ qkv,
                bf16* __restrict__ yh, bf16* __restrict__ yl) {
    int q0 = blockIdx.x * AQ;
    int h  = blockIdx.y, b = blockIdx.z;
    int tid = threadIdx.x;
    int a = tid >> 2;
    int dg = (tid & 3) * 16;
    __shared__ float sK[AKT][HD];
    __shared__ float sV[AKT][HD];
    const float* base = qkv + (long)b * TT * 3 * CC;
    const float scale = 0.125f;

    float qr[2][16], o[2][16];
    float m[2] = {-1e30f, -1e30f}, l[2] = {0.f, 0.f};
    #pragma unroll
    for (int r = 0; r < 2; r++) {
        int qg = q0 + 2 * a + r;
        #pragma unroll
        for (int i = 0; i < 16; i++) {
            qr[r][i] = base[(long)qg * 3 * CC + h * HD + dg + i] * scale;
            o[r][i] = 0.f;
        }
    }
    int nkt = q0 / AKT + 1;
    for (int kt = 0; kt < nkt; kt++) {
        int k0 = kt * AKT;
        __syncthreads();
        for (int it = tid; it < AKT * HD / 4; it += 128) {
            int row = it >> 4;
            int c4  = (it & 15) * 4;
            const float* kp = base + (long)(k0 + row) * 3 * CC + CC + h * HD + c4;
            const float* vp = base + (long)(k0 + row) * 3 * CC + 2 * CC + h * HD + c4;
            *(float4*)&sK[row][c4] = *(const float4*)kp;
            *(float4*)&sV[row][c4] = *(const float4*)vp;
        }
        __syncthreads();
        for (int jc = 0; jc < 4; jc++) {
            float s[2][16];
            #pragma unroll
            for (int j = 0; j < 16; j++) {
                int jj = jc * 16 + j;
                float p0 = 0.f, p1 = 0.f;
                #pragma unroll
                for (int i = 0; i < 16; i++) {
                    float kv = sK[jj][dg + i];
                    p0 += qr[0][i] * kv;
                    p1 += qr[1][i] * kv;
                }
                p0 += __shfl_xor_sync(0xffffffffu, p0, 1);
                p0 += __shfl_xor_sync(0xffffffffu, p0, 2);
                p1 += __shfl_xor_sync(0xffffffffu, p1, 1);
                p1 += __shfl_xor_sync(0xffffffffu, p1, 2);
                s[0][j] = p0; s[1][j] = p1;
            }
            #pragma unroll
            for (int r = 0; r < 2; r++) {
                int qg = q0 + 2 * a + r;
                float mx = m[r];
                #pragma unroll
                for (int j = 0; j < 16; j++) {
                    int kj = k0 + jc * 16 + j;
                    if (kj > qg) s[r][j] = -1e30f;
                    mx = fmaxf(mx, s[r][j]);
                }
                float corr = __expf(m[r] - mx);
                m[r] = mx;
                l[r] *= corr;
                #pragma unroll
                for (int i = 0; i < 16; i++) o[r][i] *= corr;
                #pragma unroll
                for (int j = 0; j < 16; j++) {
                    float p = __expf(s[r][j] - mx);
                    l[r] += p;
                    int jj = jc * 16 + j;
                    #pragma unroll
                    for (int i = 0; i < 16; i++)
                        o[r][i] += p * sV[jj][dg + i];
                }
            }
        }
    }
    #pragma unroll
    for (int r = 0; r < 2; r++) {
        int qg = q0 + 2 * a + r;
        float inv = 1.f / l[r];
        #pragma unroll
        for (int i = 0; i < 16; i++) {
            float v = o[r][i] * inv;
            long ofs = ((long)b * TT + qg) * CC + h * HD + dg + i;
            bf16 hh = __float2bfloat16(v);
            yh[ofs] = hh;
            yl[ofs] = __float2bfloat16(v - __bfloat162float(hh));
        }
    }
}

// ---------------- mma.sync split-bf16 GEMM ----------------
// D[M,N] = A[M,K] * B[N,K]^T fp32 via 3 bf16 MMA passes.
// CTA tile BMxM 128N, BK=32, 256 threads (8 warps 2 x 4).
// 2 CTAs/SM target: smem 2 stages, register-lean inner loop ordering.
#define B_TILE_B 10240              // 128 * 80

template<int BM, int EPI>
__global__ __launch_bounds__(256, 2)
void mma_gemm(const bf16* __restrict__ Ah, const bf16* __restrict__ Al,
              const bf16* __restrict__ Bh, const bf16* __restrict__ Bl,
              const float* __restrict__ bias, const float* __restrict__ res,
              float* __restrict__ C, bf16* __restrict__ Ch, bf16* __restrict__ Cl,
              int Ndim, int Kdim) {
    constexpr int A_TILE = BM * 80;
    constexpr int STAGE  = 2 * A_TILE + 2 * B_TILE_B;
    constexpr int NI     = BM / 32;          // i-tiles per warp (m dir)

    extern __shared__ char smemraw[];
    uint32_t sb = smem_u32(smemraw);
    int tid = threadIdx.x, w = tid >> 5, lane = tid & 31;
    int m0 = blockIdx.x * BM, n0 = blockIdx.y * 128;
    int wm = w >> 2, wn = w & 3;

    float acc[NI][4][4];
    #pragma unroll
    for (int i = 0; i < NI; i++)
        #pragma unroll
        for (int j = 0; j < 4; j++)
            #pragma unroll
            for (int r = 0; r < 4; r++) acc[i][j][r] = 0.f;

    auto load_stage = [&](int s, int c) {
        int k0 = c * 32;
        uint32_t st = sb + s * STAGE;
        // A hi/lo: BM*4 16B-chunks each
        #pragma unroll
        for (int ch = tid; ch < BM * 4; ch += 256) {
            int row = ch >> 2, cc4 = ch & 3;
            const bf16* gh = Ah + (long)(m0 + row) * Kdim + k0 + cc4 * 8;
            const bf16* gl = Al + (long)(m0 + row) * Kdim + k0 + cc4 * 8;
            uint32_t d = st + row * 80 + cc4 * 16;
            cp16(d, gh, 16);
            cp16(d + A_TILE, gl, 16);
        }
        // B hi/lo: 128*4 chunks each, zfill at N edge
        #pragma unroll
        for (int ch = tid; ch < 512; ch += 256) {
            int row = ch >> 2, cc4 = ch & 3;
            int n = n0 + row;
            int ok = (n < Ndim);
            int nn = ok ? n : 0;
            int ssz = ok ? 16 : 0;
            const bf16* gh = Bh + (long)nn * Kdim + k0 + cc4 * 8;
            const bf16* gl = Bl + (long)nn * Kdim + k0 + cc4 * 8;
            uint32_t d = st + 2 * A_TILE + row * 80 + cc4 * 16;
            cp16(d, gh, ssz);
            cp16(d + B_TILE_B, gl, ssz);
        }
    };

    const int NC = Kdim >> 5;

    load_stage(0, 0);
    asm volatile("cp.async.commit_group;" ::: "memory");

    for (int c = 0; c < NC; c++) {
        int s = c & 1;
        if (c + 1 < NC) {
            load_stage(s ^ 1, c + 1);
            asm volatile("cp.async.commit_group;" ::: "memory");
            asm volatile("cp.async.wait_group 1;" ::: "memory");
        } else {
            asm volatile("cp.async.wait_group 0;" ::: "memory");
        }
        __syncthreads();

        uint32_t base = sb + s * STAGE;
        #pragma unroll
        for (int kk = 0; kk < 2; kk++) {
            int kb = kk * 16 + ((lane >> 4) << 3);
            int kbB = kk * 16;
            // ---- A hi, B hi, hi*hi ----
            uint32_t ah[NI][4];
            #pragma unroll
            for (int i = 0; i < NI; i++) {
                int r = wm * (NI * 16) + i * 16 + (lane & 15);
                ldm4(ah[i], base + (uint32_t)(r * 80 + kb * 2));
            }
            uint32_t bh[4][2];
            #pragma unroll
            for (int jp = 0; jp < 2; jp++) {
                int mat = lane >> 3;
                int r   = wn * 32 + jp * 16 + ((mat >> 1) << 3) + (lane & 7);
                int kc  = kbB + ((mat & 1) << 3);
                uint32_t t0[4];
                ldm4(t0, base + 2 * A_TILE + (uint32_t)(r * 80 + kc * 2));
                bh[2 * jp][0] = t0[0]; bh[2 * jp][1] = t0[1];
                bh[2 * jp + 1][0] = t0[2]; bh[2 * jp + 1][1] = t0[3];
            }
            #pragma unroll
            for (int i = 0; i < NI; i++)
                #pragma unroll
                for (int j = 0; j < 4; j++)
                    mma16816(acc[i][j], ah[i], bh[j]);
            // ---- B lo, ah*bl ----
            {
                uint32_t bl[4][2];
                #pragma unroll
                for (int jp = 0; jp < 2; jp++) {
                    int mat = lane >> 3;
                    int r   = wn * 32 + jp * 16 + ((mat >> 1) << 3) + (lane & 7);
                    int kc  = kbB + ((mat & 1) << 3);
                    uint32_t t1[4];
                    ldm4(t1, base + 2 * A_TILE + B_TILE_B + (uint32_t)(r * 80 + kc * 2));
                    bl[2 * jp][0] = t1[0]; bl[2 * jp][1] = t1[1];
                    bl[2 * jp + 1][0] = t1[2]; bl[2 * jp + 1][1] = t1[3];
                }
                #pragma unroll
                for (int i = 0; i < NI; i++)
                    #pragma unroll
                    for (int j = 0; j < 4; j++)
                        mma16816(acc[i][j], ah[i], bl[j]);
            }
            // ---- A lo, al*bh (ah dead -> regs reusable) ----
            {
                uint32_t al[NI][4];
                #pragma unroll
                for (int i = 0; i < NI; i++) {
                    int r = wm * (NI * 16) + i * 16 + (lane & 15);
                    ldm4(al[i], base + A_TILE + (uint32_t)(r * 80 + kb * 2));
                }
                #pragma unroll
                for (int i = 0; i < NI; i++)
                    #pragma unroll
                    for (int j = 0; j < 4; j++)
                        mma16816(acc[i][j], al[i], bh[j]);
            }
        }
        __syncthreads();
    }

    // ---- epilogue ----
    #pragma unroll
    for (int i = 0; i < NI; i++) {
        int row0 = m0 + wm * (NI * 16) + i * 16 + (lane >> 2);
        #pragma unroll
        for (int j = 0; j < 4; j++) {
            int col = n0 + wn * 32 + j * 8 + 2 * (lane & 3);
            #pragma unroll
            for (int r = 0; r < 4; r++) {
                int rr = row0 + (r >> 1) * 8;
                int cc = col + (r & 1);
                if (cc < Ndim) {
                    float v = acc[i][j][r];
                    if (bias) v += __ldg(bias + cc);
                    long o = (long)rr * Ndim + cc;
                    if (EPI == 1) v += res[o];
                    if (EPI == 2) {
                        v = 0.5f * v * (1.f + erff(v * 0.70710678118654752f));
                        bf16 hh = __float2bfloat16(v);
                        Ch[o] = hh;
                        Cl[o] = __float2bfloat16(v - __bfloat162float(hh));
                    } else {
                        C[o] = v;
                    }
                }
            }
        }
    }
}

#define SMEM_BM128 (2 * (2 * 128 * 80 + 2 * B_TILE_B))   // 81920
#define SMEM_BM64  (2 * (2 * 64 * 80 + 2 * B_TILE_B))    // 61440

// ---------------- Host orchestration ----------------
extern "C" void kernel_launch(void* const* d_in, const int* in_sizes, int n_in,
                              void* d_out, int out_size) {
    const int*   idx     = (const int*)  d_in[0];
    const float* tok_emb = (const float*)d_in[1];
    const float* pos_emb = (const float*)d_in[2];
    const float* ln1_w   = (const float*)d_in[3];
    const float* ln1_b   = (const float*)d_in[4];
    const float* w_qkv   = (const float*)d_in[5];
    const float* b_qkv   = (const float*)d_in[6];
    const float* w_proj  = (const float*)d_in[7];
    const float* b_proj  = (const float*)d_in[8];
    const float* ln2_w   = (const float*)d_in[9];
    const float* ln2_b   = (const float*)d_in[10];
    const float* w_fc    = (const float*)d_in[11];
    const float* b_fc    = (const float*)d_in[12];
    const float* w_fc2   = (const float*)d_in[13];
    const float* b_fc2   = (const float*)d_in[14];
    const float* lnf_w   = (const float*)d_in[15];
    const float* lnf_b   = (const float*)d_in[16];
    float* out = (float*)d_out;

    cudaFuncSetAttribute(mma_gemm<128, 0>, cudaFuncAttributeMaxDynamicSharedMemorySize, SMEM_BM128);
    cudaFuncSetAttribute(mma_gemm<128, 2>, cudaFuncAttributeMaxDynamicSharedMemorySize, SMEM_BM128);
    cudaFuncSetAttribute(mma_gemm<64, 1>,  cudaFuncAttributeMaxDynamicSharedMemorySize, SMEM_BM64);

    float *x, *qkv;
    cudaGetSymbolAddress((void**)&x,   g_x);
    cudaGetSymbolAddress((void**)&qkv, g_qkv);
    bf16 *ah, *al, *fh, *fl;
    bf16 *wqh, *wql, *wph, *wpl, *wfh, *wfl, *w2h, *w2l, *eh, *el;
    cudaGetSymbolAddress((void**)&ah,  g_ah);      cudaGetSymbolAddress((void**)&al,  g_al);
    cudaGetSymbolAddress((void**)&fh,  g_fh);      cudaGetSymbolAddress((void**)&fl,  g_fl);
    cudaGetSymbolAddress((void**)&wqh, g_wqkv_h);  cudaGetSymbolAddress((void**)&wql, g_wqkv_l);
    cudaGetSymbolAddress((void**)&wph, g_wproj_h); cudaGetSymbolAddress((void**)&wpl, g_wproj_l);
    cudaGetSymbolAddress((void**)&wfh, g_wfc_h);   cudaGetSymbolAddress((void**)&wfl, g_wfc_l);
    cudaGetSymbolAddress((void**)&w2h, g_wfc2_h);  cudaGetSymbolAddress((void**)&w2l, g_wfc2_l);
    cudaGetSymbolAddress((void**)&eh,  g_emb_h);   cudaGetSymbolAddress((void**)&el,  g_emb_l);

    // ---- weight preprocessing ----
    wt_cvt<<<dim3(3 * CC / 32, CC / 32, LL), 256>>>(w_qkv,  wqh, wql, CC, 3 * CC);
    wt_cvt<<<dim3(CC / 32, CC / 32, LL), 256>>>(w_proj, wph, wpl, CC, CC);
    wt_cvt<<<dim3(4 * CC / 32, CC / 32, LL), 256>>>(w_fc,   wfh, wfl, CC, 4 * CC);
    wt_cvt<<<dim3(CC / 32, 4 * CC / 32, LL), 256>>>(w_fc2,  w2h, w2l, 4 * CC, CC);
    {
        int n = VV * CC;
        cvt_act<<<(n + 255) / 256, 256>>>(tok_emb, eh, el, n);
    }

    // ---- embedding ----
    {
        int n = MM * CC;
        embed_kernel<<<(n + 255) / 256, 256>>>(idx, tok_emb, pos_emb, x);
    }

    for (int l = 0; l < LL; l++) {
        // LN1 -> QKV GEMM (fp32 out)
        ln_kernel<<<MM, 256>>>(x, ah, al, ln1_w + (long)l * CC, ln1_b + (long)l * CC);
        mma_gemm<128, 0><<<dim3(MM / 128, 3 * CC / 128), 256, SMEM_BM128>>>(
            ah, al, wqh + (long)l * 3 * CC * CC, wql + (long)l * 3 * CC * CC,
            b_qkv + (long)l * 3 * CC, nullptr, qkv, nullptr, nullptr, 3 * CC, CC);
        // attention -> bf16 hi/lo
        attn_flash<<<dim3(TT / AQ, HH, BB), 128>>>(qkv, ah, al);
        // proj + residual -> x   (BM=64: 192 CTAs)
        mma_gemm<64, 1><<<dim3(MM / 64, CC / 128), 256, SMEM_BM64>>>(
            ah, al, wph + (long)l * CC * CC, wpl + (long)l * CC * CC,
            b_proj + (long)l * CC, x, x, nullptr, nullptr, CC, CC);
        // LN2 -> FC1 + GELU -> bf16 hi/lo
        ln_kernel<<<MM, 256>>>(x, ah, al, ln2_w + (long)l * CC, ln2_b + (long)l * CC);
        mma_gemm<128, 2><<<dim3(MM / 128, 4 * CC / 128), 256, SMEM_BM128>>>(
            ah, al, wfh + (long)l * 4 * CC * CC, wfl + (long)l * 4 * CC * CC,
            b_fc + (long)l * 4 * CC, nullptr, nullptr, fh, fl, 4 * CC, CC);
        // FC2 + residual -> x   (BM=64: 192 CTAs)
        mma_gemm<64, 1><<<dim3(MM / 64, CC / 128), 256, SMEM_BM64>>>(
            fh, fl, w2h + (long)l * 4 * CC * CC, w2l + (long)l * 4 * CC * CC,
            b_fc2 + (long)l * CC, x, x, nullptr, nullptr, CC, 4 * CC);
    }

    // final LN + tied head
    ln_kernel<<<MM, 256>>>(x, ah, al, lnf_w, lnf_b);
    mma_gemm<128, 0><<<dim3(MM / 128, (VV + 127) / 128), 256, SMEM_BM128>>>(
        ah, al, eh, el, nullptr, nullptr, out, nullptr, nullptr, VV, CC);
}